// round 12
// baseline (speedup 1.0000x reference)
#include <cuda_runtime.h>

#define N_FWD  8192
#define T_LEN  4096
#define PAD    2048
#define B_MAX  64
#define FROW   4104           // g_F row stride in float2 (4097 rounded up)
#define FTH    1024
#define ITH    256

// Scalar padding (fwd kernel, two scalar arrays)
#define PHYS(i) ((i) + ((i) >> 3))
#define FWD_PAD 9216          // PHYS(8191)=9214 -> 9216
// Complex padding (cwt kernel, interleaved float2, radix-16 stride pattern)
#define P16(i)  ((i) + ((i) >> 4))
#define INV_CP  4352          // P16(4095)=4350 -> 4352 float2

#define LOG_OFF (-9.0109133472792881f)   // -ln(8192): folds 1/n into the log

__device__ float2 g_F[B_MAX * FROW];   // half spectra F[k], k in [0,4096]

__device__ __forceinline__ void cmulf(float& zr, float& zi,
                                      float ar, float ai, float br, float bi) {
    zr = ar * br - ai * bi;
    zi = ar * bi + ai * br;
}

// ===========================================================================
// FORWARD kernel (radix-8, unchanged — ~7 us of the total)
// ===========================================================================
template<bool FWD>
__device__ __forceinline__ void bfly8(float* xr, float* xi)
{
    const float C = 0.70710678118654752440f;
    float t0r=xr[0]+xr[4], t0i=xi[0]+xi[4];
    float t4r=xr[0]-xr[4], t4i=xi[0]-xi[4];
    float t1r=xr[1]+xr[5], t1i=xi[1]+xi[5];
    float t5r=xr[1]-xr[5], t5i=xi[1]-xi[5];
    float t2r=xr[2]+xr[6], t2i=xi[2]+xi[6];
    float t6r=xr[2]-xr[6], t6i=xi[2]-xi[6];
    float t3r=xr[3]+xr[7], t3i=xi[3]+xi[7];
    float t7r=xr[3]-xr[7], t7i=xi[3]-xi[7];

    float u0r=t0r+t2r, u0i=t0i+t2i;
    float u1r=t0r-t2r, u1i=t0i-t2i;
    float u2r=t1r+t3r, u2i=t1i+t3i;
    float u3r=t1r-t3r, u3i=t1i-t3i;
    xr[0]=u0r+u2r; xi[0]=u0i+u2i;
    xr[4]=u0r-u2r; xi[4]=u0i-u2i;
    if (FWD) { xr[2]=u1r+u3i; xi[2]=u1i-u3r; xr[6]=u1r-u3i; xi[6]=u1i+u3r; }
    else     { xr[2]=u1r-u3i; xi[2]=u1i+u3r; xr[6]=u1r+u3i; xi[6]=u1i-u3r; }

    float a5r,a5i,a6r,a6i,a7r,a7i;
    if (FWD) {
        a5r =  C*(t5r+t5i);  a5i =  C*(t5i-t5r);
        a6r =  t6i;          a6i = -t6r;
        a7r =  C*(t7i-t7r);  a7i = -C*(t7r+t7i);
    } else {
        a5r =  C*(t5r-t5i);  a5i =  C*(t5r+t5i);
        a6r = -t6i;          a6i =  t6r;
        a7r = -C*(t7r+t7i);  a7i =  C*(t7r-t7i);
    }
    float v0r=t4r+a6r, v0i=t4i+a6i;
    float v1r=t4r-a6r, v1i=t4i-a6i;
    float v2r=a5r+a7r, v2i=a5i+a7i;
    float v3r=a5r-a7r, v3i=a5i-a7i;
    xr[1]=v0r+v2r; xi[1]=v0i+v2i;
    xr[5]=v0r-v2r; xi[5]=v0i-v2i;
    if (FWD) { xr[3]=v1r+v3i; xi[3]=v1i-v3r; xr[7]=v1r-v3i; xi[7]=v1i+v3r; }
    else     { xr[3]=v1r-v3i; xi[3]=v1i+v3r; xr[7]=v1r+v3i; xi[7]=v1i-v3r; }
}

__device__ __forceinline__ void store8(float* dr, float* di,
                                       const float* xr, const float* xi,
                                       int o, int m, float w1r, float w1i)
{
    float w2r = w1r*w1r - w1i*w1i, w2i = 2.0f*w1r*w1i;
    float w3r = w2r*w1r - w2i*w1i, w3i = w2r*w1i + w2i*w1r;
    float w4r = w2r*w2r - w2i*w2i, w4i = 2.0f*w2r*w2i;
    float w5r = w4r*w1r - w4i*w1i, w5i = w4r*w1i + w4i*w1r;
    float w6r = w3r*w3r - w3i*w3i, w6i = 2.0f*w3r*w3i;
    float w7r = w4r*w3r - w4i*w3i, w7i = w4r*w3i + w4i*w3r;

    int p;
    p = PHYS(o);         dr[p] = xr[0];                     di[p] = xi[0];
    p = PHYS(o + m);     dr[p] = xr[1]*w1r - xi[1]*w1i;     di[p] = xr[1]*w1i + xi[1]*w1r;
    p = PHYS(o + 2*m);   dr[p] = xr[2]*w2r - xi[2]*w2i;     di[p] = xr[2]*w2i + xi[2]*w2r;
    p = PHYS(o + 3*m);   dr[p] = xr[3]*w3r - xi[3]*w3i;     di[p] = xr[3]*w3i + xi[3]*w3r;
    p = PHYS(o + 4*m);   dr[p] = xr[4]*w4r - xi[4]*w4i;     di[p] = xr[4]*w4i + xi[4]*w4r;
    p = PHYS(o + 5*m);   dr[p] = xr[5]*w5r - xi[5]*w5i;     di[p] = xr[5]*w5i + xi[5]*w5r;
    p = PHYS(o + 6*m);   dr[p] = xr[6]*w6r - xi[6]*w6i;     di[p] = xr[6]*w6i + xi[6]*w6r;
    p = PHYS(o + 7*m);   dr[p] = xr[7]*w7r - xi[7]*w7i;     di[p] = xr[7]*w7i + xi[7]*w7r;
}

__device__ __forceinline__ void fwd_stage(const float* sr, const float* si,
                                          float* dr, float* di, int m, int tid)
{
    float xr[8], xi[8];
    #pragma unroll
    for (int q = 0; q < 8; ++q) {
        int p = PHYS(tid + q * 1024);
        xr[q] = sr[p]; xi[q] = si[p];
    }
    bfly8<true>(xr, xi);
    int k = tid & (m - 1), jm = tid - k;
    float ss, cc;                                  // e^{-2 pi i jm/8192}
    sincospif((float)jm * (1.0f / 4096.0f), &ss, &cc);
    store8(dr, di, xr, xi, 8 * jm + k, m, cc, -ss);
}

extern __shared__ float sm_[];

__global__ void __launch_bounds__(FTH, 1)
fwd_fft_kernel(const float* __restrict__ in)
{
    float* Ar = sm_;
    float* Ai = sm_ + FWD_PAD;
    float* Br = sm_ + 2 * FWD_PAD;
    float* Bi = sm_ + 3 * FWD_PAD;

    const int b = blockIdx.x, tid = threadIdx.x;
    const float* x = in + b * T_LEN;

    {
        float xr[8], xi[8];
        #pragma unroll
        for (int q = 0; q < 8; ++q) {
            int i = tid + q * 1024;
            int src;
            if (i < PAD)              src = PAD - 1 - i;
            else if (i < PAD + T_LEN) src = i - PAD;
            else                      src = (2 * T_LEN + PAD - 1) - i;
            xr[q] = x[src]; xi[q] = 0.0f;
        }
        bfly8<true>(xr, xi);
        float ss, cc;
        sincospif((float)tid * (1.0f / 4096.0f), &ss, &cc);
        store8(Ar, Ai, xr, xi, 8 * tid, 1, cc, -ss);
    }
    __syncthreads();
    fwd_stage(Ar, Ai, Br, Bi,   8, tid); __syncthreads();
    fwd_stage(Br, Bi, Ar, Ai,  64, tid); __syncthreads();
    fwd_stage(Ar, Ai, Br, Bi, 512, tid); __syncthreads();

    float2* Fo = g_F + b * FROW;
    #pragma unroll
    for (int q = 0; q < 4; ++q) {
        int k = tid + q * 1024;
        float ur = Br[PHYS(k)],        ui = Bi[PHYS(k)];
        float vr = Br[PHYS(k + 4096)], vi = Bi[PHYS(k + 4096)];
        Fo[k] = make_float2(ur + vr, ui + vi);
        if (k == 0) Fo[4096] = make_float2(ur - vr, ui - vi);
    }
}

// ===========================================================================
// CWT inverse kernel: radix-16 Stockham, register-lean R4-style fused
// butterfly (in-place step1, group-wise finish+store). 3 CTAs/SM target.
// ===========================================================================

// T[b][r1] = e^{+i pi b r1 / 8}  (inverse intra-16 twiddles)
#define CQ16 0.70710678118654752440f
#define C816 0.92387953251128675613f
#define S816 0.38268343236508977173f

// In-place inverse radix-4 over stride-4 groups: slot b+4*r1 after.
__device__ __forceinline__ void step1_inplace(float* sr, float* si)
{
    #pragma unroll
    for (int b = 0; b < 4; ++b) {
        float p0r=sr[b],    p0i=si[b];
        float p1r=sr[b+4],  p1i=si[b+4];
        float p2r=sr[b+8],  p2i=si[b+8];
        float p3r=sr[b+12], p3i=si[b+12];
        float u0r=p0r+p2r, u0i=p0i+p2i;
        float u1r=p0r-p2r, u1i=p0i-p2i;
        float u2r=p1r+p3r, u2i=p1i+p3i;
        float u3r=p1r-p3r, u3i=p1i-p3i;
        sr[b]    = u0r+u2r; si[b]    = u0i+u2i;
        sr[b+4]  = u1r-u3i; si[b+4]  = u1i+u3r;   // * (+i)
        sr[b+8]  = u0r-u2r; si[b+8]  = u0i-u2i;
        sr[b+12] = u1r+u3i; si[b+12] = u1i-u3r;   // * (-i)
    }
}

// Finish (T-mult + outer radix-4) group-by-group, applying output twiddles
// c_r = c0 * w1^r, storing to padded float2 smem. Low register pressure.
__device__ __forceinline__ void finish_store16(float2* d,
                                               const float* sr, const float* si,
                                               int o, int m,
                                               float c0r, float c0i,
                                               float w1r, float w1i)
{
    const float Tr[4][4] = {{1,1,1,1},
                            {1, C816,  CQ16,  S816},
                            {1, CQ16, 0.0f,  -CQ16},
                            {1, S816, -CQ16, -C816}};
    const float Ti[4][4] = {{0,0,0,0},
                            {0, S816,  CQ16,  C816},
                            {0, CQ16, 1.0f,   CQ16},
                            {0, C816,  CQ16, -S816}};

    float w2r,w2i,w4r,w4i,w8r,w8i,w12r,w12i;
    cmulf(w2r,w2i, w1r,w1i, w1r,w1i);
    cmulf(w4r,w4i, w2r,w2i, w2r,w2i);
    cmulf(w8r,w8i, w4r,w4i, w4r,w4i);
    cmulf(w12r,w12i, w8r,w8i, w4r,w4i);

    float cbr = c0r, cbi = c0i;
    #pragma unroll
    for (int r1 = 0; r1 < 4; ++r1) {
        if (r1) { float tr,ti; cmulf(tr,ti, cbr,cbi, w1r,w1i); cbr=tr; cbi=ti; }

        float z0r,z0i,z1r,z1i,z2r,z2i,z3r,z3i;
        cmulf(z0r,z0i, sr[4*r1+0],si[4*r1+0], Tr[0][r1],Ti[0][r1]);
        cmulf(z1r,z1i, sr[4*r1+1],si[4*r1+1], Tr[1][r1],Ti[1][r1]);
        cmulf(z2r,z2i, sr[4*r1+2],si[4*r1+2], Tr[2][r1],Ti[2][r1]);
        cmulf(z3r,z3i, sr[4*r1+3],si[4*r1+3], Tr[3][r1],Ti[3][r1]);

        float u0r=z0r+z2r, u0i=z0i+z2i;
        float u1r=z0r-z2r, u1i=z0i-z2i;
        float u2r=z1r+z3r, u2i=z1i+z3i;
        float u3r=z1r-z3r, u3i=z1i-z3i;

        float y0r=u0r+u2r, y0i=u0i+u2i;
        float y1r=u1r-u3i, y1i=u1i+u3r;
        float y2r=u0r-u2r, y2i=u0i-u2i;
        float y3r=u1r+u3i, y3i=u1i-u3r;

        float c4r,c4i,c8r,c8i,c12r,c12i;
        cmulf(c4r,c4i,   cbr,cbi, w4r,w4i);
        cmulf(c8r,c8i,   cbr,cbi, w8r,w8i);
        cmulf(c12r,c12i, cbr,cbi, w12r,w12i);

        d[P16(o + r1*m)]        = make_float2(y0r*cbr  - y0i*cbi,   y0r*cbi  + y0i*cbr);
        d[P16(o + (r1+4)*m)]    = make_float2(y1r*c4r  - y1i*c4i,   y1r*c4i  + y1i*c4r);
        d[P16(o + (r1+8)*m)]    = make_float2(y2r*c8r  - y2i*c8i,   y2r*c8i  + y2i*c8r);
        d[P16(o + (r1+12)*m)]   = make_float2(y3r*c12r - y3i*c12i,  y3r*c12i + y3i*c12r);
    }
}

__global__ void __launch_bounds__(ITH, 3)
cwt_kernel(const float* __restrict__ wft, float* __restrict__ out, int S)
{
    float2* A  = (float2*)sm_;
    float2* Bb = A + INV_CP;

    const int tid = threadIdx.x;
    const int s = blockIdx.x % S, b = blockIdx.x / S;
    const float2* __restrict__ F = g_F + b * FROW;
    const float*  __restrict__ w = wft + (size_t)s * N_FWD;

    float2 fn = F[4096];
    float  gn = w[4096];
    float  nyr = fn.x * gn, nyi = fn.y * gn;

    // Hoisted, pass-invariant twiddle bases (2 sincospif per thread).
    float sA, cA;                                   // A = e^{+2 pi i tid/8192}
    sincospif((float)tid * (1.0f / 4096.0f), &sA, &cA);
    float w1r = cA * cA - sA * sA;                  // stage-1 base = A^2
    float w1i = 2.0f * cA * sA;
    const int jm2 = tid & ~15;
    float s2s, s2c;                                 // e^{+2 pi i jm2/4096}
    sincospif((float)jm2 * (1.0f / 2048.0f), &s2s, &s2c);

    // B(q) = e^{+i pi q/16} constants for the pass-1 rotation
    const float BQr[16] = { 1.0f,  0.98078528f,  0.92387953f,  0.83146961f,
                            0.70710678f,  0.55557023f,  0.38268343f,  0.19509032f,
                            0.0f, -0.19509032f, -0.38268343f, -0.55557023f,
                           -0.70710678f, -0.83146961f, -0.92387953f, -0.98078528f };
    const float BQi[16] = { 0.0f,  0.19509032f,  0.38268343f,  0.55557023f,
                            0.70710678f,  0.83146961f,  0.92387953f,  0.98078528f,
                            1.0f,  0.98078528f,  0.92387953f,  0.83146961f,
                            0.70710678f,  0.55557023f,  0.38268343f,  0.19509032f };

    const float Tr[4][4] = {{1,1,1,1},
                            {1, C816,  CQ16,  S816},
                            {1, CQ16, 0.0f,  -CQ16},
                            {1, S816, -CQ16, -C816}};
    const float Ti[4][4] = {{0,0,0,0},
                            {0, S816,  CQ16,  C816},
                            {0, CQ16, 1.0f,   CQ16},
                            {0, C816,  CQ16, -S816}};

    #pragma unroll
    for (int pass = 0; pass < 2; ++pass) {
        float sr[16], si[16];

        // ---- stage 1 (m=1): fused global load + spectrum multiply.
        // Pass-1 rotation e^{+2pi i k/8192} = A(tid)*B(q); A folded into c0.
        #pragma unroll
        for (int q = 0; q < 16; ++q) {
            int k = tid + q * 256;
            float2 f = F[k];
            float  g = w[k];
            float vr = f.x * g, vi = f.y * g;
            if (pass) {
                float br = BQr[q], bi = BQi[q];
                float r2 = vr * br - vi * bi;
                float i2 = vr * bi + vi * br;
                vr = r2; vi = i2;
            }
            sr[q] = vr; si[q] = vi;
        }
        step1_inplace(sr, si);
        if (pass == 0) finish_store16(A, sr, si, 16 * tid, 1, 1.0f, 0.0f, w1r, w1i);
        else           finish_store16(A, sr, si, 16 * tid, 1, cA,   sA,   w1r, w1i);
        __syncthreads();

        // ---- stage 2 (m=16)
        #pragma unroll
        for (int q = 0; q < 16; ++q) {
            float2 v = A[P16(tid + q * 256)];
            sr[q] = v.x; si[q] = v.y;
        }
        step1_inplace(sr, si);
        finish_store16(Bb, sr, si, 16 * jm2 + (tid & 15), 16, 1.0f, 0.0f, s2c, s2s);
        __syncthreads();

        // ---- stage 3 (m=256, jm=0, W=1): fused Nyquist + log|.| + output.
        // Only r = r1+4 and r1+8 land in the output window.
        #pragma unroll
        for (int q = 0; q < 16; ++q) {
            float2 v = Bb[P16(tid + q * 256)];
            sr[q] = v.x; si[q] = v.y;
        }
        step1_inplace(sr, si);

        float nr = pass ? -nyr : nyr;
        float ni = pass ? -nyi : nyi;
        float* ob = out + (size_t)blockIdx.x * T_LEN + 2 * tid + pass;

        #pragma unroll
        for (int r1 = 0; r1 < 4; ++r1) {
            float z0r,z0i,z1r,z1i,z2r,z2i,z3r,z3i;
            cmulf(z0r,z0i, sr[4*r1+0],si[4*r1+0], Tr[0][r1],Ti[0][r1]);
            cmulf(z1r,z1i, sr[4*r1+1],si[4*r1+1], Tr[1][r1],Ti[1][r1]);
            cmulf(z2r,z2i, sr[4*r1+2],si[4*r1+2], Tr[2][r1],Ti[2][r1]);
            cmulf(z3r,z3i, sr[4*r1+3],si[4*r1+3], Tr[3][r1],Ti[3][r1]);

            float u0r=z0r+z2r, u0i=z0i+z2i;
            float u1r=z0r-z2r, u1i=z0i-z2i;
            float u2r=z1r+z3r, u2i=z1i+z3i;
            float u3r=z1r-z3r, u3i=z1i-z3i;

            // r = r1+4 (r2=1): y = u1 + i*u3 (inverse)
            float a1 = (u1r - u3i) + nr, b1 = (u1i + u3r) + ni;
            ob[512 * r1]       = fmaf(0.5f, __logf(a1 * a1 + b1 * b1), LOG_OFF);
            // r = r1+8 (r2=2): y = u0 - u2
            float a2 = (u0r - u2r) + nr, b2 = (u0i - u2i) + ni;
            ob[512 * (r1 + 4)] = fmaf(0.5f, __logf(a2 * a2 + b2 * b2), LOG_OFF);
        }
        // Barrier ordering for the next pass is provided by the barrier
        // after the next pass's stage-1 store (Bb is not written until
        // after that barrier).
    }
}

// ---------------------------------------------------------------------------
extern "C" void kernel_launch(void* const* d_in, const int* in_sizes, int n_in,
                              void* d_out, int out_size)
{
    const float* in  = (const float*)d_in[0];
    const float* wft = (const float*)d_in[1];
    float* out = (float*)d_out;

    const int B = in_sizes[0] / T_LEN;     // 64
    const int S = in_sizes[1] / N_FWD;     // 75

    const int fwd_smem = 4 * FWD_PAD * sizeof(float);      // 147456 B
    const int cwt_smem = 2 * INV_CP * sizeof(float2);      //  69632 B
    cudaFuncSetAttribute(fwd_fft_kernel,
                         cudaFuncAttributeMaxDynamicSharedMemorySize, fwd_smem);
    cudaFuncSetAttribute(cwt_kernel,
                         cudaFuncAttributeMaxDynamicSharedMemorySize, cwt_smem);

    fwd_fft_kernel<<<B, FTH, fwd_smem>>>(in);
    cwt_kernel<<<B * S, ITH, cwt_smem>>>(wft, out, S);
}

// round 13
// speedup vs baseline: 1.2722x; 1.2722x over previous
#include <cuda_runtime.h>

#define N_FWD  8192
#define T_LEN  4096
#define PAD    2048
#define B_MAX  64
#define FROW   4104           // g_F row stride in float2 (4097 rounded up)
#define FTH    1024
#define ITH    256

// Scalar padding (fwd kernel, two scalar arrays)
#define PHYS(i) ((i) + ((i) >> 3))
#define FWD_PAD 9216          // PHYS(8191)=9214 -> 9216
// Complex padding (cwt kernel, interleaved float2, radix-16 stride pattern)
#define P16(i)  ((i) + ((i) >> 4))
#define INV_CP  4352          // P16(4095)=4350 -> 4352 float2

#define LOG_OFF (-9.0109133472792881f)   // -ln(8192): folds 1/n into the log

__device__ float2 g_F[B_MAX * FROW];   // half spectra F[k], k in [0,4096]

__device__ __forceinline__ void cmulf(float& zr, float& zi,
                                      float ar, float ai, float br, float bi) {
    zr = ar * br - ai * bi;
    zi = ar * bi + ai * br;
}

// ===========================================================================
// FORWARD kernel (radix-8, unchanged)
// ===========================================================================
template<bool FWD>
__device__ __forceinline__ void bfly8(float* xr, float* xi)
{
    const float C = 0.70710678118654752440f;
    float t0r=xr[0]+xr[4], t0i=xi[0]+xi[4];
    float t4r=xr[0]-xr[4], t4i=xi[0]-xi[4];
    float t1r=xr[1]+xr[5], t1i=xi[1]+xi[5];
    float t5r=xr[1]-xr[5], t5i=xi[1]-xi[5];
    float t2r=xr[2]+xr[6], t2i=xi[2]+xi[6];
    float t6r=xr[2]-xr[6], t6i=xi[2]-xi[6];
    float t3r=xr[3]+xr[7], t3i=xi[3]+xi[7];
    float t7r=xr[3]-xr[7], t7i=xi[3]-xi[7];

    float u0r=t0r+t2r, u0i=t0i+t2i;
    float u1r=t0r-t2r, u1i=t0i-t2i;
    float u2r=t1r+t3r, u2i=t1i+t3i;
    float u3r=t1r-t3r, u3i=t1i-t3i;
    xr[0]=u0r+u2r; xi[0]=u0i+u2i;
    xr[4]=u0r-u2r; xi[4]=u0i-u2i;
    if (FWD) { xr[2]=u1r+u3i; xi[2]=u1i-u3r; xr[6]=u1r-u3i; xi[6]=u1i+u3r; }
    else     { xr[2]=u1r-u3i; xi[2]=u1i+u3r; xr[6]=u1r+u3i; xi[6]=u1i-u3r; }

    float a5r,a5i,a6r,a6i,a7r,a7i;
    if (FWD) {
        a5r =  C*(t5r+t5i);  a5i =  C*(t5i-t5r);
        a6r =  t6i;          a6i = -t6r;
        a7r =  C*(t7i-t7r);  a7i = -C*(t7r+t7i);
    } else {
        a5r =  C*(t5r-t5i);  a5i =  C*(t5r+t5i);
        a6r = -t6i;          a6i =  t6r;
        a7r = -C*(t7r+t7i);  a7i =  C*(t7r-t7i);
    }
    float v0r=t4r+a6r, v0i=t4i+a6i;
    float v1r=t4r-a6r, v1i=t4i-a6i;
    float v2r=a5r+a7r, v2i=a5i+a7i;
    float v3r=a5r-a7r, v3i=a5i-a7i;
    xr[1]=v0r+v2r; xi[1]=v0i+v2i;
    xr[5]=v0r-v2r; xi[5]=v0i-v2i;
    if (FWD) { xr[3]=v1r+v3i; xi[3]=v1i-v3r; xr[7]=v1r-v3i; xi[7]=v1i+v3r; }
    else     { xr[3]=v1r-v3i; xi[3]=v1i+v3r; xr[7]=v1r+v3i; xi[7]=v1i-v3r; }
}

__device__ __forceinline__ void store8(float* dr, float* di,
                                       const float* xr, const float* xi,
                                       int o, int m, float w1r, float w1i)
{
    float w2r = w1r*w1r - w1i*w1i, w2i = 2.0f*w1r*w1i;
    float w3r = w2r*w1r - w2i*w1i, w3i = w2r*w1i + w2i*w1r;
    float w4r = w2r*w2r - w2i*w2i, w4i = 2.0f*w2r*w2i;
    float w5r = w4r*w1r - w4i*w1i, w5i = w4r*w1i + w4i*w1r;
    float w6r = w3r*w3r - w3i*w3i, w6i = 2.0f*w3r*w3i;
    float w7r = w4r*w3r - w4i*w3i, w7i = w4r*w3i + w4i*w3r;

    int p;
    p = PHYS(o);         dr[p] = xr[0];                     di[p] = xi[0];
    p = PHYS(o + m);     dr[p] = xr[1]*w1r - xi[1]*w1i;     di[p] = xr[1]*w1i + xi[1]*w1r;
    p = PHYS(o + 2*m);   dr[p] = xr[2]*w2r - xi[2]*w2i;     di[p] = xr[2]*w2i + xi[2]*w2r;
    p = PHYS(o + 3*m);   dr[p] = xr[3]*w3r - xi[3]*w3i;     di[p] = xr[3]*w3i + xi[3]*w3r;
    p = PHYS(o + 4*m);   dr[p] = xr[4]*w4r - xi[4]*w4i;     di[p] = xr[4]*w4i + xi[4]*w4r;
    p = PHYS(o + 5*m);   dr[p] = xr[5]*w5r - xi[5]*w5i;     di[p] = xr[5]*w5i + xi[5]*w5r;
    p = PHYS(o + 6*m);   dr[p] = xr[6]*w6r - xi[6]*w6i;     di[p] = xr[6]*w6i + xi[6]*w6r;
    p = PHYS(o + 7*m);   dr[p] = xr[7]*w7r - xi[7]*w7i;     di[p] = xr[7]*w7i + xi[7]*w7r;
}

__device__ __forceinline__ void fwd_stage(const float* sr, const float* si,
                                          float* dr, float* di, int m, int tid)
{
    float xr[8], xi[8];
    #pragma unroll
    for (int q = 0; q < 8; ++q) {
        int p = PHYS(tid + q * 1024);
        xr[q] = sr[p]; xi[q] = si[p];
    }
    bfly8<true>(xr, xi);
    int k = tid & (m - 1), jm = tid - k;
    float ss, cc;                                  // e^{-2 pi i jm/8192}
    sincospif((float)jm * (1.0f / 4096.0f), &ss, &cc);
    store8(dr, di, xr, xi, 8 * jm + k, m, cc, -ss);
}

extern __shared__ float sm_[];

__global__ void __launch_bounds__(FTH, 1)
fwd_fft_kernel(const float* __restrict__ in)
{
    float* Ar = sm_;
    float* Ai = sm_ + FWD_PAD;
    float* Br = sm_ + 2 * FWD_PAD;
    float* Bi = sm_ + 3 * FWD_PAD;

    const int b = blockIdx.x, tid = threadIdx.x;
    const float* x = in + b * T_LEN;

    {
        float xr[8], xi[8];
        #pragma unroll
        for (int q = 0; q < 8; ++q) {
            int i = tid + q * 1024;
            int src;
            if (i < PAD)              src = PAD - 1 - i;
            else if (i < PAD + T_LEN) src = i - PAD;
            else                      src = (2 * T_LEN + PAD - 1) - i;
            xr[q] = x[src]; xi[q] = 0.0f;
        }
        bfly8<true>(xr, xi);
        float ss, cc;
        sincospif((float)tid * (1.0f / 4096.0f), &ss, &cc);
        store8(Ar, Ai, xr, xi, 8 * tid, 1, cc, -ss);
    }
    __syncthreads();
    fwd_stage(Ar, Ai, Br, Bi,   8, tid); __syncthreads();
    fwd_stage(Br, Bi, Ar, Ai,  64, tid); __syncthreads();
    fwd_stage(Ar, Ai, Br, Bi, 512, tid); __syncthreads();

    float2* Fo = g_F + b * FROW;
    #pragma unroll
    for (int q = 0; q < 4; ++q) {
        int k = tid + q * 1024;
        float ur = Br[PHYS(k)],        ui = Bi[PHYS(k)];
        float vr = Br[PHYS(k + 4096)], vi = Bi[PHYS(k + 4096)];
        Fo[k] = make_float2(ur + vr, ui + vi);
        if (k == 0) Fo[4096] = make_float2(ur - vr, ui - vi);
    }
}

// ===========================================================================
// CWT inverse kernel: radix-16 Stockham (R11 structure, 256 thr, 2 CTAs/SM).
// Delta vs R11: (a) stage-1 F-loads and rotations are predicated off where
// wft underflows to 0 (most of the spectrum for low-frequency scales);
// (b) stage 3 computes only the 8 of 16 outputs in the output window.
// ===========================================================================

__device__ __forceinline__ void bfly16_inv(const float* xr, const float* xi,
                                           float* yr, float* yi)
{
    float sr[16], si[16];
    #pragma unroll
    for (int b = 0; b < 4; ++b) {
        float p0r=xr[b],    p0i=xi[b];
        float p1r=xr[b+4],  p1i=xi[b+4];
        float p2r=xr[b+8],  p2i=xi[b+8];
        float p3r=xr[b+12], p3i=xi[b+12];
        float u0r=p0r+p2r, u0i=p0i+p2i;
        float u1r=p0r-p2r, u1i=p0i-p2i;
        float u2r=p1r+p3r, u2i=p1i+p3i;
        float u3r=p1r-p3r, u3i=p1i-p3i;
        sr[b]    = u0r+u2r; si[b]    = u0i+u2i;
        sr[b+4]  = u1r-u3i; si[b+4]  = u1i+u3r;   // * (+i)
        sr[b+8]  = u0r-u2r; si[b+8]  = u0i-u2i;
        sr[b+12] = u1r+u3i; si[b+12] = u1i-u3r;   // * (-i)
    }

    const float CQ = 0.70710678118654752440f;
    const float C8 = 0.92387953251128675613f;
    const float S8 = 0.38268343236508977173f;
    const float Tr[4][4] = {{1,1,1,1},
                            {1, C8,  CQ,  S8},
                            {1, CQ, 0.0f, -CQ},
                            {1, S8, -CQ, -C8}};
    const float Ti[4][4] = {{0,0,0,0},
                            {0, S8,  CQ,  C8},
                            {0, CQ, 1.0f,  CQ},
                            {0, C8,  CQ, -S8}};

    #pragma unroll
    for (int r1 = 0; r1 < 4; ++r1) {
        float zr[4], zi[4];
        #pragma unroll
        for (int b = 0; b < 4; ++b)
            cmulf(zr[b], zi[b], sr[4*r1+b], si[4*r1+b], Tr[b][r1], Ti[b][r1]);
        float u0r=zr[0]+zr[2], u0i=zi[0]+zi[2];
        float u1r=zr[0]-zr[2], u1i=zi[0]-zi[2];
        float u2r=zr[1]+zr[3], u2i=zi[1]+zi[3];
        float u3r=zr[1]-zr[3], u3i=zi[1]-zi[3];
        yr[r1]    = u0r+u2r; yi[r1]    = u0i+u2i;
        yr[r1+4]  = u1r-u3i; yi[r1+4]  = u1i+u3r;
        yr[r1+8]  = u0r-u2r; yi[r1+8]  = u0i-u2i;
        yr[r1+12] = u1r+u3i; yi[r1+12] = u1i-u3r;
    }
}

// Partial inverse 16-pt DFT: compute only outputs r = 4..11 into y[r-4].
__device__ __forceinline__ void bfly16_inv_mid(const float* xr, const float* xi,
                                               float* yr, float* yi)
{
    float sr[16], si[16];
    #pragma unroll
    for (int b = 0; b < 4; ++b) {
        float p0r=xr[b],    p0i=xi[b];
        float p1r=xr[b+4],  p1i=xi[b+4];
        float p2r=xr[b+8],  p2i=xi[b+8];
        float p3r=xr[b+12], p3i=xi[b+12];
        float u0r=p0r+p2r, u0i=p0i+p2i;
        float u1r=p0r-p2r, u1i=p0i-p2i;
        float u2r=p1r+p3r, u2i=p1i+p3i;
        float u3r=p1r-p3r, u3i=p1i-p3i;
        sr[b]    = u0r+u2r; si[b]    = u0i+u2i;
        sr[b+4]  = u1r-u3i; si[b+4]  = u1i+u3r;
        sr[b+8]  = u0r-u2r; si[b+8]  = u0i-u2i;
        sr[b+12] = u1r+u3i; si[b+12] = u1i-u3r;
    }

    const float CQ = 0.70710678118654752440f;
    const float C8 = 0.92387953251128675613f;
    const float S8 = 0.38268343236508977173f;
    const float Tr[4][4] = {{1,1,1,1},
                            {1, C8,  CQ,  S8},
                            {1, CQ, 0.0f, -CQ},
                            {1, S8, -CQ, -C8}};
    const float Ti[4][4] = {{0,0,0,0},
                            {0, S8,  CQ,  C8},
                            {0, CQ, 1.0f,  CQ},
                            {0, C8,  CQ, -S8}};

    #pragma unroll
    for (int r1 = 0; r1 < 4; ++r1) {
        float zr[4], zi[4];
        #pragma unroll
        for (int b = 0; b < 4; ++b)
            cmulf(zr[b], zi[b], sr[4*r1+b], si[4*r1+b], Tr[b][r1], Ti[b][r1]);
        float u0r=zr[0]+zr[2], u0i=zi[0]+zi[2];
        float u1r=zr[0]-zr[2], u1i=zi[0]-zi[2];
        float u2r=zr[1]+zr[3], u2i=zi[1]+zi[3];
        float u3r=zr[1]-zr[3], u3i=zi[1]-zi[3];
        // r = r1+4 (r2=1): y = u1 + i*u3 ; r = r1+8 (r2=2): y = u0 - u2
        yr[r1]     = u1r - u3i; yi[r1]     = u1i + u3r;
        yr[r1 + 4] = u0r - u2r; yi[r1 + 4] = u0i - u2i;
    }
}

// Store 16 outputs with twiddles c_r = c0 * w1^r via a depth<=4 c-tree.
__device__ __forceinline__ void store16c(float2* d,
                                         const float* yr, const float* yi,
                                         int o, int m,
                                         float c0r, float c0i,
                                         float w1r, float w1i)
{
    float w2r = w1r*w1r - w1i*w1i, w2i = 2.0f*w1r*w1i;
    float w4r = w2r*w2r - w2i*w2i, w4i = 2.0f*w2r*w2i;
    float w8r = w4r*w4r - w4i*w4i, w8i = 2.0f*w4r*w4i;

    float cr[16], ci[16];
    cr[0] = c0r; ci[0] = c0i;
    cmulf(cr[1], ci[1], cr[0], ci[0], w1r, w1i);
    cmulf(cr[2], ci[2], cr[0], ci[0], w2r, w2i);
    cmulf(cr[3], ci[3], cr[1], ci[1], w2r, w2i);
    #pragma unroll
    for (int r = 4; r < 8; ++r)  cmulf(cr[r], ci[r], cr[r-4], ci[r-4], w4r, w4i);
    #pragma unroll
    for (int r = 8; r < 16; ++r) cmulf(cr[r], ci[r], cr[r-8], ci[r-8], w8r, w8i);

    #pragma unroll
    for (int r = 0; r < 16; ++r)
        d[P16(o + r*m)] = make_float2(yr[r]*cr[r] - yi[r]*ci[r],
                                      yr[r]*ci[r] + yi[r]*cr[r]);
}

__global__ void __launch_bounds__(ITH, 2)
cwt_kernel(const float* __restrict__ wft, float* __restrict__ out, int S)
{
    float2* A  = (float2*)sm_;
    float2* Bb = A + INV_CP;

    const int tid = threadIdx.x;
    const int s = blockIdx.x % S, b = blockIdx.x / S;
    const float2* __restrict__ F = g_F + b * FROW;
    const float*  __restrict__ w = wft + (size_t)s * N_FWD;

    float2 fn = F[4096];
    float  gn = w[4096];
    float  nyr = fn.x * gn, nyi = fn.y * gn;

    // Hoisted, pass-invariant twiddle bases (2 sincospif per thread total).
    float sA, cA;                                   // A = e^{+2 pi i tid/8192}
    sincospif((float)tid * (1.0f / 4096.0f), &sA, &cA);
    float w1r = cA * cA - sA * sA;                  // stage-1 base = A^2
    float w1i = 2.0f * cA * sA;
    const int jm2 = tid & ~15;                      // stage-2 jm
    float s2s, s2c;                                 // e^{+2 pi i jm2/4096}
    sincospif((float)jm2 * (1.0f / 2048.0f), &s2s, &s2c);

    // B(q) = e^{+i pi q/16} constants for the pass-1 rotation
    const float BQr[16] = { 1.0f,  0.98078528f,  0.92387953f,  0.83146961f,
                            0.70710678f,  0.55557023f,  0.38268343f,  0.19509032f,
                            0.0f, -0.19509032f, -0.38268343f, -0.55557023f,
                           -0.70710678f, -0.83146961f, -0.92387953f, -0.98078528f };
    const float BQi[16] = { 0.0f,  0.19509032f,  0.38268343f,  0.55557023f,
                            0.70710678f,  0.83146961f,  0.92387953f,  0.98078528f,
                            1.0f,  0.98078528f,  0.92387953f,  0.83146961f,
                            0.70710678f,  0.55557023f,  0.38268343f,  0.19509032f };

    float ev[8];   // pass-0 log values (same thread & columns in pass 1)

    #pragma unroll
    for (int pass = 0; pass < 2; ++pass) {
        float xr[16], xi[16], yr[16], yi[16];

        // ---- stage 1 (m=1, jm=tid): fused global load + spectrum multiply.
        // wft underflows to exact 0 beyond each scale's Gaussian support:
        // predicate off the F load + rotation there (bit-identical result,
        // no LDG issued for dead lanes/warps).
        #pragma unroll
        for (int q = 0; q < 16; ++q) {
            int k = tid + q * 256;
            float g = w[k];
            float vr = 0.0f, vi = 0.0f;
            if (g != 0.0f) {
                float2 f = F[k];
                vr = f.x * g; vi = f.y * g;
                if (pass) {
                    float br = BQr[q], bi = BQi[q];
                    float r2 = vr * br - vi * bi;
                    float i2 = vr * bi + vi * br;
                    vr = r2; vi = i2;
                }
            }
            xr[q] = vr; xi[q] = vi;
        }
        bfly16_inv(xr, xi, yr, yi);
        if (pass == 0) store16c(A, yr, yi, 16 * tid, 1, 1.0f, 0.0f, w1r, w1i);
        else           store16c(A, yr, yi, 16 * tid, 1, cA,   sA,   w1r, w1i);
        __syncthreads();

        // ---- stage 2 (m=16)
        #pragma unroll
        for (int q = 0; q < 16; ++q) {
            float2 v = A[P16(tid + q * 256)];
            xr[q] = v.x; xi[q] = v.y;
        }
        bfly16_inv(xr, xi, yr, yi);
        {
            int k2 = tid & 15;
            store16c(Bb, yr, yi, 16 * jm2 + k2, 16, 1.0f, 0.0f, s2c, s2s);
        }
        __syncthreads();

        // ---- stage 3 (m=256, jm=0, W=1): partial butterfly (r=4..11 only)
        // fused with Nyquist + log|.| + output.
        #pragma unroll
        for (int q = 0; q < 16; ++q) {
            float2 v = Bb[P16(tid + q * 256)];
            xr[q] = v.x; xi[q] = v.y;
        }
        bfly16_inv_mid(xr, xi, yr, yi);   // yr/yi[0..7] == outputs r=4..11

        float nr = pass ? -nyr : nyr;
        float ni = pass ? -nyi : nyi;
        if (pass == 0) {
            #pragma unroll
            for (int j = 0; j < 8; ++j) {
                float a = yr[j] + nr, b2 = yi[j] + ni;
                ev[j] = fmaf(0.5f, __logf(a * a + b2 * b2), LOG_OFF);
            }
        } else {
            float2* o2 = (float2*)(out + (size_t)blockIdx.x * T_LEN);
            #pragma unroll
            for (int j = 0; j < 8; ++j) {
                float a = yr[j] + nr, b2 = yi[j] + ni;
                float lg = fmaf(0.5f, __logf(a * a + b2 * b2), LOG_OFF);
                o2[tid + 256 * j] = make_float2(ev[j], lg);
            }
        }
        // Barrier ordering for the next pass is provided by the barrier
        // after the next pass's stage-1 store.
    }
}

// ---------------------------------------------------------------------------
extern "C" void kernel_launch(void* const* d_in, const int* in_sizes, int n_in,
                              void* d_out, int out_size)
{
    const float* in  = (const float*)d_in[0];
    const float* wft = (const float*)d_in[1];
    float* out = (float*)d_out;

    const int B = in_sizes[0] / T_LEN;     // 64
    const int S = in_sizes[1] / N_FWD;     // 75

    const int fwd_smem = 4 * FWD_PAD * sizeof(float);      // 147456 B
    const int cwt_smem = 2 * INV_CP * sizeof(float2);      //  69632 B
    cudaFuncSetAttribute(fwd_fft_kernel,
                         cudaFuncAttributeMaxDynamicSharedMemorySize, fwd_smem);
    cudaFuncSetAttribute(cwt_kernel,
                         cudaFuncAttributeMaxDynamicSharedMemorySize, cwt_smem);

    fwd_fft_kernel<<<B, FTH, fwd_smem>>>(in);
    cwt_kernel<<<B * S, ITH, cwt_smem>>>(wft, out, S);
}

// round 14
// speedup vs baseline: 1.3483x; 1.0598x over previous
#include <cuda_runtime.h>

#define N_FWD  8192
#define T_LEN  4096
#define PAD    2048
#define B_MAX  64
#define FROW   4104           // g_F row stride in float2 (4097 rounded up)
#define FTH    1024
#define ITH    256

// Scalar padding (fwd kernel, two scalar arrays)
#define PHYS(i) ((i) + ((i) >> 3))
#define FWD_PAD 9216          // PHYS(8191)=9214 -> 9216
// Complex padding (cwt kernel, interleaved float2, radix-16 stride pattern)
#define P16(i)  ((i) + ((i) >> 4))
#define INV_CP  4352          // P16(4095)=4350 -> 4352 float2

#define LOG_OFF (-9.0109133472792881f)   // -ln(8192): folds 1/n into the log

__device__ float2 g_F[B_MAX * FROW];   // half spectra F[k], k in [0,4096]

__device__ __forceinline__ void cmulf(float& zr, float& zi,
                                      float ar, float ai, float br, float bi) {
    zr = ar * br - ai * bi;
    zi = ar * bi + ai * br;
}

// ===========================================================================
// FORWARD kernel (radix-8, unchanged)
// ===========================================================================
template<bool FWD>
__device__ __forceinline__ void bfly8(float* xr, float* xi)
{
    const float C = 0.70710678118654752440f;
    float t0r=xr[0]+xr[4], t0i=xi[0]+xi[4];
    float t4r=xr[0]-xr[4], t4i=xi[0]-xi[4];
    float t1r=xr[1]+xr[5], t1i=xi[1]+xi[5];
    float t5r=xr[1]-xr[5], t5i=xi[1]-xi[5];
    float t2r=xr[2]+xr[6], t2i=xi[2]+xi[6];
    float t6r=xr[2]-xr[6], t6i=xi[2]-xi[6];
    float t3r=xr[3]+xr[7], t3i=xi[3]+xi[7];
    float t7r=xr[3]-xr[7], t7i=xi[3]-xi[7];

    float u0r=t0r+t2r, u0i=t0i+t2i;
    float u1r=t0r-t2r, u1i=t0i-t2i;
    float u2r=t1r+t3r, u2i=t1i+t3i;
    float u3r=t1r-t3r, u3i=t1i-t3i;
    xr[0]=u0r+u2r; xi[0]=u0i+u2i;
    xr[4]=u0r-u2r; xi[4]=u0i-u2i;
    if (FWD) { xr[2]=u1r+u3i; xi[2]=u1i-u3r; xr[6]=u1r-u3i; xi[6]=u1i+u3r; }
    else     { xr[2]=u1r-u3i; xi[2]=u1i+u3r; xr[6]=u1r+u3i; xi[6]=u1i-u3r; }

    float a5r,a5i,a6r,a6i,a7r,a7i;
    if (FWD) {
        a5r =  C*(t5r+t5i);  a5i =  C*(t5i-t5r);
        a6r =  t6i;          a6i = -t6r;
        a7r =  C*(t7i-t7r);  a7i = -C*(t7r+t7i);
    } else {
        a5r =  C*(t5r-t5i);  a5i =  C*(t5r+t5i);
        a6r = -t6i;          a6i =  t6r;
        a7r = -C*(t7r+t7i);  a7i =  C*(t7r-t7i);
    }
    float v0r=t4r+a6r, v0i=t4i+a6i;
    float v1r=t4r-a6r, v1i=t4i-a6i;
    float v2r=a5r+a7r, v2i=a5i+a7i;
    float v3r=a5r-a7r, v3i=a5i-a7i;
    xr[1]=v0r+v2r; xi[1]=v0i+v2i;
    xr[5]=v0r-v2r; xi[5]=v0i-v2i;
    if (FWD) { xr[3]=v1r+v3i; xi[3]=v1i-v3r; xr[7]=v1r-v3i; xi[7]=v1i+v3r; }
    else     { xr[3]=v1r-v3i; xi[3]=v1i+v3r; xr[7]=v1r+v3i; xi[7]=v1i-v3r; }
}

__device__ __forceinline__ void store8(float* dr, float* di,
                                       const float* xr, const float* xi,
                                       int o, int m, float w1r, float w1i)
{
    float w2r = w1r*w1r - w1i*w1i, w2i = 2.0f*w1r*w1i;
    float w3r = w2r*w1r - w2i*w1i, w3i = w2r*w1i + w2i*w1r;
    float w4r = w2r*w2r - w2i*w2i, w4i = 2.0f*w2r*w2i;
    float w5r = w4r*w1r - w4i*w1i, w5i = w4r*w1i + w4i*w1r;
    float w6r = w3r*w3r - w3i*w3i, w6i = 2.0f*w3r*w3i;
    float w7r = w4r*w3r - w4i*w3i, w7i = w4r*w3i + w4i*w3r;

    int p;
    p = PHYS(o);         dr[p] = xr[0];                     di[p] = xi[0];
    p = PHYS(o + m);     dr[p] = xr[1]*w1r - xi[1]*w1i;     di[p] = xr[1]*w1i + xi[1]*w1r;
    p = PHYS(o + 2*m);   dr[p] = xr[2]*w2r - xi[2]*w2i;     di[p] = xr[2]*w2i + xi[2]*w2r;
    p = PHYS(o + 3*m);   dr[p] = xr[3]*w3r - xi[3]*w3i;     di[p] = xr[3]*w3i + xi[3]*w3r;
    p = PHYS(o + 4*m);   dr[p] = xr[4]*w4r - xi[4]*w4i;     di[p] = xr[4]*w4i + xi[4]*w4r;
    p = PHYS(o + 5*m);   dr[p] = xr[5]*w5r - xi[5]*w5i;     di[p] = xr[5]*w5i + xi[5]*w5r;
    p = PHYS(o + 6*m);   dr[p] = xr[6]*w6r - xi[6]*w6i;     di[p] = xr[6]*w6i + xi[6]*w6r;
    p = PHYS(o + 7*m);   dr[p] = xr[7]*w7r - xi[7]*w7i;     di[p] = xr[7]*w7i + xi[7]*w7r;
}

__device__ __forceinline__ void fwd_stage(const float* sr, const float* si,
                                          float* dr, float* di, int m, int tid)
{
    float xr[8], xi[8];
    #pragma unroll
    for (int q = 0; q < 8; ++q) {
        int p = PHYS(tid + q * 1024);
        xr[q] = sr[p]; xi[q] = si[p];
    }
    bfly8<true>(xr, xi);
    int k = tid & (m - 1), jm = tid - k;
    float ss, cc;                                  // e^{-2 pi i jm/8192}
    sincospif((float)jm * (1.0f / 4096.0f), &ss, &cc);
    store8(dr, di, xr, xi, 8 * jm + k, m, cc, -ss);
}

extern __shared__ float sm_[];

__global__ void __launch_bounds__(FTH, 1)
fwd_fft_kernel(const float* __restrict__ in)
{
    float* Ar = sm_;
    float* Ai = sm_ + FWD_PAD;
    float* Br = sm_ + 2 * FWD_PAD;
    float* Bi = sm_ + 3 * FWD_PAD;

    const int b = blockIdx.x, tid = threadIdx.x;
    const float* x = in + b * T_LEN;

    {
        float xr[8], xi[8];
        #pragma unroll
        for (int q = 0; q < 8; ++q) {
            int i = tid + q * 1024;
            int src;
            if (i < PAD)              src = PAD - 1 - i;
            else if (i < PAD + T_LEN) src = i - PAD;
            else                      src = (2 * T_LEN + PAD - 1) - i;
            xr[q] = x[src]; xi[q] = 0.0f;
        }
        bfly8<true>(xr, xi);
        float ss, cc;
        sincospif((float)tid * (1.0f / 4096.0f), &ss, &cc);
        store8(Ar, Ai, xr, xi, 8 * tid, 1, cc, -ss);
    }
    __syncthreads();
    fwd_stage(Ar, Ai, Br, Bi,   8, tid); __syncthreads();
    fwd_stage(Br, Bi, Ar, Ai,  64, tid); __syncthreads();
    fwd_stage(Ar, Ai, Br, Bi, 512, tid); __syncthreads();

    float2* Fo = g_F + b * FROW;
    #pragma unroll
    for (int q = 0; q < 4; ++q) {
        int k = tid + q * 1024;
        float ur = Br[PHYS(k)],        ui = Bi[PHYS(k)];
        float vr = Br[PHYS(k + 4096)], vi = Bi[PHYS(k + 4096)];
        Fo[k] = make_float2(ur + vr, ui + vi);
        if (k == 0) Fo[4096] = make_float2(ur - vr, ui - vi);
    }
}

// ===========================================================================
// CWT inverse kernel: radix-16 Stockham (R11 structure, 256 thr, 2 CTAs/SM).
// Single delta vs R11: stage 3 computes only the 8 of 16 outputs that land
// in the output window (bfly16_inv_mid) — pure FMA-pipe reduction.
// ===========================================================================

__device__ __forceinline__ void bfly16_inv(const float* xr, const float* xi,
                                           float* yr, float* yi)
{
    float sr[16], si[16];
    #pragma unroll
    for (int b = 0; b < 4; ++b) {
        float p0r=xr[b],    p0i=xi[b];
        float p1r=xr[b+4],  p1i=xi[b+4];
        float p2r=xr[b+8],  p2i=xi[b+8];
        float p3r=xr[b+12], p3i=xi[b+12];
        float u0r=p0r+p2r, u0i=p0i+p2i;
        float u1r=p0r-p2r, u1i=p0i-p2i;
        float u2r=p1r+p3r, u2i=p1i+p3i;
        float u3r=p1r-p3r, u3i=p1i-p3i;
        sr[b]    = u0r+u2r; si[b]    = u0i+u2i;
        sr[b+4]  = u1r-u3i; si[b+4]  = u1i+u3r;   // * (+i)
        sr[b+8]  = u0r-u2r; si[b+8]  = u0i-u2i;
        sr[b+12] = u1r+u3i; si[b+12] = u1i-u3r;   // * (-i)
    }

    const float CQ = 0.70710678118654752440f;
    const float C8 = 0.92387953251128675613f;
    const float S8 = 0.38268343236508977173f;
    const float Tr[4][4] = {{1,1,1,1},
                            {1, C8,  CQ,  S8},
                            {1, CQ, 0.0f, -CQ},
                            {1, S8, -CQ, -C8}};
    const float Ti[4][4] = {{0,0,0,0},
                            {0, S8,  CQ,  C8},
                            {0, CQ, 1.0f,  CQ},
                            {0, C8,  CQ, -S8}};

    #pragma unroll
    for (int r1 = 0; r1 < 4; ++r1) {
        float zr[4], zi[4];
        #pragma unroll
        for (int b = 0; b < 4; ++b)
            cmulf(zr[b], zi[b], sr[4*r1+b], si[4*r1+b], Tr[b][r1], Ti[b][r1]);
        float u0r=zr[0]+zr[2], u0i=zi[0]+zi[2];
        float u1r=zr[0]-zr[2], u1i=zi[0]-zi[2];
        float u2r=zr[1]+zr[3], u2i=zi[1]+zi[3];
        float u3r=zr[1]-zr[3], u3i=zi[1]-zi[3];
        yr[r1]    = u0r+u2r; yi[r1]    = u0i+u2i;
        yr[r1+4]  = u1r-u3i; yi[r1+4]  = u1i+u3r;
        yr[r1+8]  = u0r-u2r; yi[r1+8]  = u0i-u2i;
        yr[r1+12] = u1r+u3i; yi[r1+12] = u1i-u3r;
    }
}

// Partial inverse 16-pt DFT: compute only outputs r = 4..11 into y[r-4].
__device__ __forceinline__ void bfly16_inv_mid(const float* xr, const float* xi,
                                               float* yr, float* yi)
{
    float sr[16], si[16];
    #pragma unroll
    for (int b = 0; b < 4; ++b) {
        float p0r=xr[b],    p0i=xi[b];
        float p1r=xr[b+4],  p1i=xi[b+4];
        float p2r=xr[b+8],  p2i=xi[b+8];
        float p3r=xr[b+12], p3i=xi[b+12];
        float u0r=p0r+p2r, u0i=p0i+p2i;
        float u1r=p0r-p2r, u1i=p0i-p2i;
        float u2r=p1r+p3r, u2i=p1i+p3i;
        float u3r=p1r-p3r, u3i=p1i-p3i;
        sr[b]    = u0r+u2r; si[b]    = u0i+u2i;
        sr[b+4]  = u1r-u3i; si[b+4]  = u1i+u3r;
        sr[b+8]  = u0r-u2r; si[b+8]  = u0i-u2i;
        sr[b+12] = u1r+u3i; si[b+12] = u1i-u3r;
    }

    const float CQ = 0.70710678118654752440f;
    const float C8 = 0.92387953251128675613f;
    const float S8 = 0.38268343236508977173f;
    const float Tr[4][4] = {{1,1,1,1},
                            {1, C8,  CQ,  S8},
                            {1, CQ, 0.0f, -CQ},
                            {1, S8, -CQ, -C8}};
    const float Ti[4][4] = {{0,0,0,0},
                            {0, S8,  CQ,  C8},
                            {0, CQ, 1.0f,  CQ},
                            {0, C8,  CQ, -S8}};

    #pragma unroll
    for (int r1 = 0; r1 < 4; ++r1) {
        float zr[4], zi[4];
        #pragma unroll
        for (int b = 0; b < 4; ++b)
            cmulf(zr[b], zi[b], sr[4*r1+b], si[4*r1+b], Tr[b][r1], Ti[b][r1]);
        float u0r=zr[0]+zr[2], u0i=zi[0]+zi[2];
        float u1r=zr[0]-zr[2], u1i=zi[0]-zi[2];
        float u2r=zr[1]+zr[3], u2i=zi[1]+zi[3];
        float u3r=zr[1]-zr[3], u3i=zi[1]-zi[3];
        // r = r1+4 (r2=1): y = u1 + i*u3 ; r = r1+8 (r2=2): y = u0 - u2
        yr[r1]     = u1r - u3i; yi[r1]     = u1i + u3r;
        yr[r1 + 4] = u0r - u2r; yi[r1 + 4] = u0i - u2i;
    }
}

// Store 16 outputs with twiddles c_r = c0 * w1^r via a depth<=4 c-tree.
__device__ __forceinline__ void store16c(float2* d,
                                         const float* yr, const float* yi,
                                         int o, int m,
                                         float c0r, float c0i,
                                         float w1r, float w1i)
{
    float w2r = w1r*w1r - w1i*w1i, w2i = 2.0f*w1r*w1i;
    float w4r = w2r*w2r - w2i*w2i, w4i = 2.0f*w2r*w2i;
    float w8r = w4r*w4r - w4i*w4i, w8i = 2.0f*w4r*w4i;

    float cr[16], ci[16];
    cr[0] = c0r; ci[0] = c0i;
    cmulf(cr[1], ci[1], cr[0], ci[0], w1r, w1i);
    cmulf(cr[2], ci[2], cr[0], ci[0], w2r, w2i);
    cmulf(cr[3], ci[3], cr[1], ci[1], w2r, w2i);
    #pragma unroll
    for (int r = 4; r < 8; ++r)  cmulf(cr[r], ci[r], cr[r-4], ci[r-4], w4r, w4i);
    #pragma unroll
    for (int r = 8; r < 16; ++r) cmulf(cr[r], ci[r], cr[r-8], ci[r-8], w8r, w8i);

    #pragma unroll
    for (int r = 0; r < 16; ++r)
        d[P16(o + r*m)] = make_float2(yr[r]*cr[r] - yi[r]*ci[r],
                                      yr[r]*ci[r] + yi[r]*cr[r]);
}

__global__ void __launch_bounds__(ITH, 2)
cwt_kernel(const float* __restrict__ wft, float* __restrict__ out, int S)
{
    float2* A  = (float2*)sm_;
    float2* Bb = A + INV_CP;

    const int tid = threadIdx.x;
    const int s = blockIdx.x % S, b = blockIdx.x / S;
    const float2* __restrict__ F = g_F + b * FROW;
    const float*  __restrict__ w = wft + (size_t)s * N_FWD;

    float2 fn = F[4096];
    float  gn = w[4096];
    float  nyr = fn.x * gn, nyi = fn.y * gn;

    // Hoisted, pass-invariant twiddle bases (2 sincospif per thread total).
    float sA, cA;                                   // A = e^{+2 pi i tid/8192}
    sincospif((float)tid * (1.0f / 4096.0f), &sA, &cA);
    float w1r = cA * cA - sA * sA;                  // stage-1 base = A^2
    float w1i = 2.0f * cA * sA;
    const int jm2 = tid & ~15;                      // stage-2 jm
    float s2s, s2c;                                 // e^{+2 pi i jm2/4096}
    sincospif((float)jm2 * (1.0f / 2048.0f), &s2s, &s2c);

    // B(q) = e^{+i pi q/16} constants for the pass-1 rotation
    const float BQr[16] = { 1.0f,  0.98078528f,  0.92387953f,  0.83146961f,
                            0.70710678f,  0.55557023f,  0.38268343f,  0.19509032f,
                            0.0f, -0.19509032f, -0.38268343f, -0.55557023f,
                           -0.70710678f, -0.83146961f, -0.92387953f, -0.98078528f };
    const float BQi[16] = { 0.0f,  0.19509032f,  0.38268343f,  0.55557023f,
                            0.70710678f,  0.83146961f,  0.92387953f,  0.98078528f,
                            1.0f,  0.98078528f,  0.92387953f,  0.83146961f,
                            0.70710678f,  0.55557023f,  0.38268343f,  0.19509032f };

    float ev[8];   // pass-0 log values (same thread & columns in pass 1)

    #pragma unroll
    for (int pass = 0; pass < 2; ++pass) {
        float xr[16], xi[16], yr[16], yi[16];

        // ---- stage 1 (m=1, jm=tid): fused global load + spectrum multiply.
        // Pass 1 rotation e^{+2 pi i k/8192} = A(tid) * B(q), A folded into c0.
        #pragma unroll
        for (int q = 0; q < 16; ++q) {
            int k = tid + q * 256;
            float2 f = F[k];
            float  g = w[k];
            float vr = f.x * g, vi = f.y * g;
            if (pass) {
                float br = BQr[q], bi = BQi[q];
                float r2 = vr * br - vi * bi;
                float i2 = vr * bi + vi * br;
                vr = r2; vi = i2;
            }
            xr[q] = vr; xi[q] = vi;
        }
        bfly16_inv(xr, xi, yr, yi);
        if (pass == 0) store16c(A, yr, yi, 16 * tid, 1, 1.0f, 0.0f, w1r, w1i);
        else           store16c(A, yr, yi, 16 * tid, 1, cA,   sA,   w1r, w1i);
        __syncthreads();

        // ---- stage 2 (m=16)
        #pragma unroll
        for (int q = 0; q < 16; ++q) {
            float2 v = A[P16(tid + q * 256)];
            xr[q] = v.x; xi[q] = v.y;
        }
        bfly16_inv(xr, xi, yr, yi);
        {
            int k2 = tid & 15;
            store16c(Bb, yr, yi, 16 * jm2 + k2, 16, 1.0f, 0.0f, s2c, s2s);
        }
        __syncthreads();

        // ---- stage 3 (m=256, jm=0, W=1): partial butterfly (r=4..11 only)
        // fused with Nyquist + log|.| + output.
        #pragma unroll
        for (int q = 0; q < 16; ++q) {
            float2 v = Bb[P16(tid + q * 256)];
            xr[q] = v.x; xi[q] = v.y;
        }
        bfly16_inv_mid(xr, xi, yr, yi);   // yr/yi[0..7] == outputs r=4..11

        float nr = pass ? -nyr : nyr;
        float ni = pass ? -nyi : nyi;
        if (pass == 0) {
            #pragma unroll
            for (int j = 0; j < 8; ++j) {
                float a = yr[j] + nr, b2 = yi[j] + ni;
                ev[j] = fmaf(0.5f, __logf(a * a + b2 * b2), LOG_OFF);
            }
        } else {
            float2* o2 = (float2*)(out + (size_t)blockIdx.x * T_LEN);
            #pragma unroll
            for (int j = 0; j < 8; ++j) {
                float a = yr[j] + nr, b2 = yi[j] + ni;
                float lg = fmaf(0.5f, __logf(a * a + b2 * b2), LOG_OFF);
                o2[tid + 256 * j] = make_float2(ev[j], lg);
            }
        }
        // Barrier ordering for the next pass is provided by the barrier
        // after the next pass's stage-1 store.
    }
}

// ---------------------------------------------------------------------------
extern "C" void kernel_launch(void* const* d_in, const int* in_sizes, int n_in,
                              void* d_out, int out_size)
{
    const float* in  = (const float*)d_in[0];
    const float* wft = (const float*)d_in[1];
    float* out = (float*)d_out;

    const int B = in_sizes[0] / T_LEN;     // 64
    const int S = in_sizes[1] / N_FWD;     // 75

    const int fwd_smem = 4 * FWD_PAD * sizeof(float);      // 147456 B
    const int cwt_smem = 2 * INV_CP * sizeof(float2);      //  69632 B
    cudaFuncSetAttribute(fwd_fft_kernel,
                         cudaFuncAttributeMaxDynamicSharedMemorySize, fwd_smem);
    cudaFuncSetAttribute(cwt_kernel,
                         cudaFuncAttributeMaxDynamicSharedMemorySize, cwt_smem);

    fwd_fft_kernel<<<B, FTH, fwd_smem>>>(in);
    cwt_kernel<<<B * S, ITH, cwt_smem>>>(wft, out, S);
}

// round 15
// speedup vs baseline: 1.3701x; 1.0161x over previous
#include <cuda_runtime.h>

#define N_FWD  8192
#define T_LEN  4096
#define PAD    2048
#define B_MAX  64
#define FROW   4104           // g_F row stride in float2 (4097 rounded up)
#define FTH    512
#define ITH    256

// Complex padding (interleaved float2, radix-16 stride pattern)
#define P16(i)  ((i) + ((i) >> 4))
#define INV_CP  4352          // P16(4095)=4350 -> 4352 float2
#define FWD_CP  8704          // P16(8191)=8702 -> 8704 float2

#define LOG_OFF (-9.0109133472792881f)   // -ln(8192): folds 1/n into the log

__device__ float2 g_F[B_MAX * FROW];   // half spectra F[k], k in [0,4096]

__device__ __forceinline__ void cmulf(float& zr, float& zi,
                                      float ar, float ai, float br, float bi) {
    zr = ar * br - ai * bi;
    zi = ar * bi + ai * br;
}

// ===========================================================================
// Shared: store 16 outputs with twiddles c_r = c0 * w1^r via a depth<=4
// c-tree (3 squarings + 15 independent cmuls; register-only).
// Sign-agnostic: forward passes a conjugate base w1.
// ===========================================================================
__device__ __forceinline__ void store16c(float2* d,
                                         const float* yr, const float* yi,
                                         int o, int m,
                                         float c0r, float c0i,
                                         float w1r, float w1i)
{
    float w2r = w1r*w1r - w1i*w1i, w2i = 2.0f*w1r*w1i;
    float w4r = w2r*w2r - w2i*w2i, w4i = 2.0f*w2r*w2i;
    float w8r = w4r*w4r - w4i*w4i, w8i = 2.0f*w4r*w4i;

    float cr[16], ci[16];
    cr[0] = c0r; ci[0] = c0i;
    cmulf(cr[1], ci[1], cr[0], ci[0], w1r, w1i);
    cmulf(cr[2], ci[2], cr[0], ci[0], w2r, w2i);
    cmulf(cr[3], ci[3], cr[1], ci[1], w2r, w2i);
    #pragma unroll
    for (int r = 4; r < 8; ++r)  cmulf(cr[r], ci[r], cr[r-4], ci[r-4], w4r, w4i);
    #pragma unroll
    for (int r = 8; r < 16; ++r) cmulf(cr[r], ci[r], cr[r-8], ci[r-8], w8r, w8i);

    #pragma unroll
    for (int r = 0; r < 16; ++r)
        d[P16(o + r*m)] = make_float2(yr[r]*cr[r] - yi[r]*ci[r],
                                      yr[r]*ci[r] + yi[r]*cr[r]);
}

// ===========================================================================
// 16-pt DFT butterflies (Cooley radix-4^2). INV: e^{+2pi i jr/16},
// FWD: e^{-2pi i jr/16} (i -> -i everywhere, T-matrix imag negated).
// ===========================================================================
#define CQ16 0.70710678118654752440f
#define C816 0.92387953251128675613f
#define S816 0.38268343236508977173f

__device__ __forceinline__ void bfly16_inv(const float* xr, const float* xi,
                                           float* yr, float* yi)
{
    float sr[16], si[16];
    #pragma unroll
    for (int b = 0; b < 4; ++b) {
        float p0r=xr[b],    p0i=xi[b];
        float p1r=xr[b+4],  p1i=xi[b+4];
        float p2r=xr[b+8],  p2i=xi[b+8];
        float p3r=xr[b+12], p3i=xi[b+12];
        float u0r=p0r+p2r, u0i=p0i+p2i;
        float u1r=p0r-p2r, u1i=p0i-p2i;
        float u2r=p1r+p3r, u2i=p1i+p3i;
        float u3r=p1r-p3r, u3i=p1i-p3i;
        sr[b]    = u0r+u2r; si[b]    = u0i+u2i;
        sr[b+4]  = u1r-u3i; si[b+4]  = u1i+u3r;   // u1 + i*u3
        sr[b+8]  = u0r-u2r; si[b+8]  = u0i-u2i;
        sr[b+12] = u1r+u3i; si[b+12] = u1i-u3r;   // u1 - i*u3
    }

    const float Tr[4][4] = {{1,1,1,1},
                            {1, C816,  CQ16,  S816},
                            {1, CQ16, 0.0f,  -CQ16},
                            {1, S816, -CQ16, -C816}};
    const float Ti[4][4] = {{0,0,0,0},
                            {0, S816,  CQ16,  C816},
                            {0, CQ16, 1.0f,   CQ16},
                            {0, C816,  CQ16, -S816}};

    #pragma unroll
    for (int r1 = 0; r1 < 4; ++r1) {
        float zr[4], zi[4];
        #pragma unroll
        for (int b = 0; b < 4; ++b)
            cmulf(zr[b], zi[b], sr[4*r1+b], si[4*r1+b], Tr[b][r1], Ti[b][r1]);
        float u0r=zr[0]+zr[2], u0i=zi[0]+zi[2];
        float u1r=zr[0]-zr[2], u1i=zi[0]-zi[2];
        float u2r=zr[1]+zr[3], u2i=zi[1]+zi[3];
        float u3r=zr[1]-zr[3], u3i=zi[1]-zi[3];
        yr[r1]    = u0r+u2r; yi[r1]    = u0i+u2i;
        yr[r1+4]  = u1r-u3i; yi[r1+4]  = u1i+u3r;
        yr[r1+8]  = u0r-u2r; yi[r1+8]  = u0i-u2i;
        yr[r1+12] = u1r+u3i; yi[r1+12] = u1i-u3r;
    }
}

__device__ __forceinline__ void bfly16_fwd(const float* xr, const float* xi,
                                           float* yr, float* yi)
{
    float sr[16], si[16];
    #pragma unroll
    for (int b = 0; b < 4; ++b) {
        float p0r=xr[b],    p0i=xi[b];
        float p1r=xr[b+4],  p1i=xi[b+4];
        float p2r=xr[b+8],  p2i=xi[b+8];
        float p3r=xr[b+12], p3i=xi[b+12];
        float u0r=p0r+p2r, u0i=p0i+p2i;
        float u1r=p0r-p2r, u1i=p0i-p2i;
        float u2r=p1r+p3r, u2i=p1i+p3i;
        float u3r=p1r-p3r, u3i=p1i-p3i;
        sr[b]    = u0r+u2r; si[b]    = u0i+u2i;
        sr[b+4]  = u1r+u3i; si[b+4]  = u1i-u3r;   // u1 - i*u3
        sr[b+8]  = u0r-u2r; si[b+8]  = u0i-u2i;
        sr[b+12] = u1r-u3i; si[b+12] = u1i+u3r;   // u1 + i*u3
    }

    // T[b][r1] = e^{-i pi b r1/8}: imag negated vs inverse
    const float Tr[4][4] = {{1,1,1,1},
                            {1, C816,  CQ16,  S816},
                            {1, CQ16, 0.0f,  -CQ16},
                            {1, S816, -CQ16, -C816}};
    const float Ti[4][4] = {{0,0,0,0},
                            {0, -S816, -CQ16, -C816},
                            {0, -CQ16, -1.0f, -CQ16},
                            {0, -C816, -CQ16,  S816}};

    #pragma unroll
    for (int r1 = 0; r1 < 4; ++r1) {
        float zr[4], zi[4];
        #pragma unroll
        for (int b = 0; b < 4; ++b)
            cmulf(zr[b], zi[b], sr[4*r1+b], si[4*r1+b], Tr[b][r1], Ti[b][r1]);
        float u0r=zr[0]+zr[2], u0i=zi[0]+zi[2];
        float u1r=zr[0]-zr[2], u1i=zi[0]-zi[2];
        float u2r=zr[1]+zr[3], u2i=zi[1]+zi[3];
        float u3r=zr[1]-zr[3], u3i=zi[1]-zi[3];
        yr[r1]    = u0r+u2r; yi[r1]    = u0i+u2i;
        yr[r1+4]  = u1r+u3i; yi[r1+4]  = u1i-u3r;   // u1 - i*u3
        yr[r1+8]  = u0r-u2r; yi[r1+8]  = u0i-u2i;
        yr[r1+12] = u1r-u3i; yi[r1+12] = u1i+u3r;   // u1 + i*u3
    }
}

// Partial inverse 16-pt DFT: compute only outputs r = 4..11 into y[r-4].
__device__ __forceinline__ void bfly16_inv_mid(const float* xr, const float* xi,
                                               float* yr, float* yi)
{
    float sr[16], si[16];
    #pragma unroll
    for (int b = 0; b < 4; ++b) {
        float p0r=xr[b],    p0i=xi[b];
        float p1r=xr[b+4],  p1i=xi[b+4];
        float p2r=xr[b+8],  p2i=xi[b+8];
        float p3r=xr[b+12], p3i=xi[b+12];
        float u0r=p0r+p2r, u0i=p0i+p2i;
        float u1r=p0r-p2r, u1i=p0i-p2i;
        float u2r=p1r+p3r, u2i=p1i+p3i;
        float u3r=p1r-p3r, u3i=p1i-p3i;
        sr[b]    = u0r+u2r; si[b]    = u0i+u2i;
        sr[b+4]  = u1r-u3i; si[b+4]  = u1i+u3r;
        sr[b+8]  = u0r-u2r; si[b+8]  = u0i-u2i;
        sr[b+12] = u1r+u3i; si[b+12] = u1i-u3r;
    }

    const float Tr[4][4] = {{1,1,1,1},
                            {1, C816,  CQ16,  S816},
                            {1, CQ16, 0.0f,  -CQ16},
                            {1, S816, -CQ16, -C816}};
    const float Ti[4][4] = {{0,0,0,0},
                            {0, S816,  CQ16,  C816},
                            {0, CQ16, 1.0f,   CQ16},
                            {0, C816,  CQ16, -S816}};

    #pragma unroll
    for (int r1 = 0; r1 < 4; ++r1) {
        float zr[4], zi[4];
        #pragma unroll
        for (int b = 0; b < 4; ++b)
            cmulf(zr[b], zi[b], sr[4*r1+b], si[4*r1+b], Tr[b][r1], Ti[b][r1]);
        float u0r=zr[0]+zr[2], u0i=zi[0]+zi[2];
        float u1r=zr[0]-zr[2], u1i=zi[0]-zi[2];
        float u2r=zr[1]+zr[3], u2i=zi[1]+zi[3];
        float u3r=zr[1]-zr[3], u3i=zi[1]-zi[3];
        // r = r1+4 (r2=1): y = u1 + i*u3 ; r = r1+8 (r2=2): y = u0 - u2
        yr[r1]     = u1r - u3i; yi[r1]     = u1i + u3r;
        yr[r1 + 4] = u0r - u2r; yi[r1 + 4] = u0i - u2i;
    }
}

extern __shared__ float sm_[];

// ===========================================================================
// FORWARD 8192-pt FFT: radix-16 x3 + final radix-2 (w=1) fused with the
// half-spectrum store. 512 threads, 3 smem round trips (was 5 with radix-8).
// ===========================================================================
__global__ void __launch_bounds__(FTH, 1)
fwd_fft_kernel(const float* __restrict__ in)
{
    float2* A  = (float2*)sm_;
    float2* Bb = A + FWD_CP;

    const int b = blockIdx.x, tid = threadIdx.x;
    const float* x = in + b * T_LEN;

    float xr[16], xi[16], yr[16], yi[16];

    // ---- stage 1 (m=1, jm=tid) fused with reflect-pad load
    #pragma unroll
    for (int q = 0; q < 16; ++q) {
        int i = tid + q * 512;
        int src;
        if (i < PAD)              src = PAD - 1 - i;
        else if (i < PAD + T_LEN) src = i - PAD;
        else                      src = (2 * T_LEN + PAD - 1) - i;
        xr[q] = x[src]; xi[q] = 0.0f;
    }
    bfly16_fwd(xr, xi, yr, yi);
    {
        float ss, cc;                       // w1 = e^{-2 pi i tid/8192}
        sincospif((float)tid * (1.0f / 4096.0f), &ss, &cc);
        store16c(A, yr, yi, 16 * tid, 1, 1.0f, 0.0f, cc, -ss);
    }
    __syncthreads();

    // ---- stage 2 (m=16)
    #pragma unroll
    for (int q = 0; q < 16; ++q) {
        float2 v = A[P16(tid + q * 512)];
        xr[q] = v.x; xi[q] = v.y;
    }
    bfly16_fwd(xr, xi, yr, yi);
    {
        int k = tid & 15, jm = tid - k;
        float ss, cc;                       // e^{-2 pi i jm/8192}
        sincospif((float)jm * (1.0f / 4096.0f), &ss, &cc);
        store16c(Bb, yr, yi, 16 * jm + k, 16, 1.0f, 0.0f, cc, -ss);
    }
    __syncthreads();

    // ---- stage 3 (m=256)
    #pragma unroll
    for (int q = 0; q < 16; ++q) {
        float2 v = Bb[P16(tid + q * 512)];
        xr[q] = v.x; xi[q] = v.y;
    }
    bfly16_fwd(xr, xi, yr, yi);
    {
        int k = tid & 255, jm = tid - k;
        float ss, cc;                       // e^{-2 pi i jm/8192}
        sincospif((float)jm * (1.0f / 4096.0f), &ss, &cc);
        store16c(A, yr, yi, 16 * jm + k, 256, 1.0f, 0.0f, cc, -ss);
    }
    __syncthreads();

    // ---- final radix-2 (m=4096, w=1): keep only k in [0,4096]
    float2* Fo = g_F + b * FROW;
    #pragma unroll
    for (int q = 0; q < 8; ++q) {
        int k = tid + q * 512;
        float2 u = A[P16(k)], v = A[P16(k + 4096)];
        Fo[k] = make_float2(u.x + v.x, u.y + v.y);
        if (k == 0) Fo[4096] = make_float2(u.x - v.x, u.y - v.y);
    }
}

// ===========================================================================
// CWT inverse kernel: radix-16 Stockham (R14 winner, byte-identical).
// ===========================================================================
__global__ void __launch_bounds__(ITH, 2)
cwt_kernel(const float* __restrict__ wft, float* __restrict__ out, int S)
{
    float2* A  = (float2*)sm_;
    float2* Bb = A + INV_CP;

    const int tid = threadIdx.x;
    const int s = blockIdx.x % S, b = blockIdx.x / S;
    const float2* __restrict__ F = g_F + b * FROW;
    const float*  __restrict__ w = wft + (size_t)s * N_FWD;

    float2 fn = F[4096];
    float  gn = w[4096];
    float  nyr = fn.x * gn, nyi = fn.y * gn;

    // Hoisted, pass-invariant twiddle bases (2 sincospif per thread total).
    float sA, cA;                                   // A = e^{+2 pi i tid/8192}
    sincospif((float)tid * (1.0f / 4096.0f), &sA, &cA);
    float w1r = cA * cA - sA * sA;                  // stage-1 base = A^2
    float w1i = 2.0f * cA * sA;
    const int jm2 = tid & ~15;                      // stage-2 jm
    float s2s, s2c;                                 // e^{+2 pi i jm2/4096}
    sincospif((float)jm2 * (1.0f / 2048.0f), &s2s, &s2c);

    // B(q) = e^{+i pi q/16} constants for the pass-1 rotation
    const float BQr[16] = { 1.0f,  0.98078528f,  0.92387953f,  0.83146961f,
                            0.70710678f,  0.55557023f,  0.38268343f,  0.19509032f,
                            0.0f, -0.19509032f, -0.38268343f, -0.55557023f,
                           -0.70710678f, -0.83146961f, -0.92387953f, -0.98078528f };
    const float BQi[16] = { 0.0f,  0.19509032f,  0.38268343f,  0.55557023f,
                            0.70710678f,  0.83146961f,  0.92387953f,  0.98078528f,
                            1.0f,  0.98078528f,  0.92387953f,  0.83146961f,
                            0.70710678f,  0.55557023f,  0.38268343f,  0.19509032f };

    float ev[8];   // pass-0 log values (same thread & columns in pass 1)

    #pragma unroll
    for (int pass = 0; pass < 2; ++pass) {
        float xr[16], xi[16], yr[16], yi[16];

        // ---- stage 1 (m=1, jm=tid): fused global load + spectrum multiply.
        // Pass 1 rotation e^{+2 pi i k/8192} = A(tid) * B(q), A folded into c0.
        #pragma unroll
        for (int q = 0; q < 16; ++q) {
            int k = tid + q * 256;
            float2 f = F[k];
            float  g = w[k];
            float vr = f.x * g, vi = f.y * g;
            if (pass) {
                float br = BQr[q], bi = BQi[q];
                float r2 = vr * br - vi * bi;
                float i2 = vr * bi + vi * br;
                vr = r2; vi = i2;
            }
            xr[q] = vr; xi[q] = vi;
        }
        bfly16_inv(xr, xi, yr, yi);
        if (pass == 0) store16c(A, yr, yi, 16 * tid, 1, 1.0f, 0.0f, w1r, w1i);
        else           store16c(A, yr, yi, 16 * tid, 1, cA,   sA,   w1r, w1i);
        __syncthreads();

        // ---- stage 2 (m=16)
        #pragma unroll
        for (int q = 0; q < 16; ++q) {
            float2 v = A[P16(tid + q * 256)];
            xr[q] = v.x; xi[q] = v.y;
        }
        bfly16_inv(xr, xi, yr, yi);
        {
            int k2 = tid & 15;
            store16c(Bb, yr, yi, 16 * jm2 + k2, 16, 1.0f, 0.0f, s2c, s2s);
        }
        __syncthreads();

        // ---- stage 3 (m=256, jm=0, W=1): partial butterfly (r=4..11 only)
        // fused with Nyquist + log|.| + output.
        #pragma unroll
        for (int q = 0; q < 16; ++q) {
            float2 v = Bb[P16(tid + q * 256)];
            xr[q] = v.x; xi[q] = v.y;
        }
        bfly16_inv_mid(xr, xi, yr, yi);   // yr/yi[0..7] == outputs r=4..11

        float nr = pass ? -nyr : nyr;
        float ni = pass ? -nyi : nyi;
        if (pass == 0) {
            #pragma unroll
            for (int j = 0; j < 8; ++j) {
                float a = yr[j] + nr, b2 = yi[j] + ni;
                ev[j] = fmaf(0.5f, __logf(a * a + b2 * b2), LOG_OFF);
            }
        } else {
            float2* o2 = (float2*)(out + (size_t)blockIdx.x * T_LEN);
            #pragma unroll
            for (int j = 0; j < 8; ++j) {
                float a = yr[j] + nr, b2 = yi[j] + ni;
                float lg = fmaf(0.5f, __logf(a * a + b2 * b2), LOG_OFF);
                o2[tid + 256 * j] = make_float2(ev[j], lg);
            }
        }
        // Barrier ordering for the next pass is provided by the barrier
        // after the next pass's stage-1 store.
    }
}

// ---------------------------------------------------------------------------
extern "C" void kernel_launch(void* const* d_in, const int* in_sizes, int n_in,
                              void* d_out, int out_size)
{
    const float* in  = (const float*)d_in[0];
    const float* wft = (const float*)d_in[1];
    float* out = (float*)d_out;

    const int B = in_sizes[0] / T_LEN;     // 64
    const int S = in_sizes[1] / N_FWD;     // 75

    const int fwd_smem = 2 * FWD_CP * sizeof(float2);      // 139264 B
    const int cwt_smem = 2 * INV_CP * sizeof(float2);      //  69632 B
    cudaFuncSetAttribute(fwd_fft_kernel,
                         cudaFuncAttributeMaxDynamicSharedMemorySize, fwd_smem);
    cudaFuncSetAttribute(cwt_kernel,
                         cudaFuncAttributeMaxDynamicSharedMemorySize, cwt_smem);

    fwd_fft_kernel<<<B, FTH, fwd_smem>>>(in);
    cwt_kernel<<<B * S, ITH, cwt_smem>>>(wft, out, S);
}